// round 5
// baseline (speedup 1.0000x reference)
#include <cuda_runtime.h>
#include <math.h>

#define BATCH 4
#define CIN 64
#define COUT 64
#define HH 192
#define WW 192
#define HW (HH*WW)          // 36864
#define CHW (CIN*HW)
#define PIX (BATCH*HW)      // 147456
#define KROWS 576           // cin*9

typedef unsigned long long ull;

__device__ __forceinline__ void fma2(ull &d, ull a, ull b) {
    asm("fma.rn.f32x2 %0, %1, %2, %0;" : "+l"(d) : "l"(a), "l"(b));
}
__device__ __forceinline__ ull pack2(float lo, float hi) {
    ull r; asm("mov.b64 %0, {%1, %2};" : "=l"(r) : "f"(lo), "f"(hi)); return r;
}
__device__ __forceinline__ void unpack2(float &lo, float &hi, ull v) {
    asm("mov.b64 {%0, %1}, %2;" : "=f"(lo), "=f"(hi) : "l"(v));
}

// ---- scratch (device globals; no runtime allocation) ----
__device__ float g_wA[KROWS*28];        // offset/mask weights, [cin*9][28] (27 used)
__device__ float g_wB[KROWS*64];        // main conv weights, [cin*9][64]
__device__ float g_off[BATCH*27*HW];    // 0..8: dy, 9..17: dx, 18..26: sigmoid(mask)
__device__ float g_mid[BATCH*COUT*HW];  // pre-BN conv output
__device__ float g_part[64*16*2];       // BN partial sums
__device__ float g_scale[COUT];
__device__ float g_shift[COUT];

// ---------------------------------------------------------------------------
// K0: transpose weights into [cin*9][oc] layouts
// ---------------------------------------------------------------------------
__global__ void k0_prep(const float* __restrict__ wp, const float* __restrict__ wm,
                        const float* __restrict__ wc) {
    int i = blockIdx.x * 256 + threadIdx.x;
    if (i < KROWS*28) {
        int row = i / 28, j = i % 28;          // row = c*9+k
        float v = 0.f;
        if (j < 18)      v = wp[j*KROWS + row];
        else if (j < 27) v = wm[(j-18)*KROWS + row];
        g_wA[i] = v;
    }
    if (i < KROWS*64) {
        int row = i / 64, o = i % 64;          // row = c*9+n
        g_wB[i] = wc[o*KROWS + row];
    }
}

// ---------------------------------------------------------------------------
// K1: 3x3 conv producing 18 offsets + 9 masks (sigmoid applied), layout
//     g_off[b][j][y][x]
// ---------------------------------------------------------------------------
__global__ void __launch_bounds__(192) k1_offconv(const float* __restrict__ x,
                                                  const float* __restrict__ bp,
                                                  const float* __restrict__ bm) {
    extern __shared__ float sw[];   // KROWS*28 floats
    int tid = threadIdx.x;
    for (int i = tid; i < KROWS*28; i += 192) sw[i] = g_wA[i];
    __syncthreads();

    int xx = tid;
    int y  = blockIdx.x;
    int b  = blockIdx.y;

    ull acc[14];
#pragma unroll
    for (int j = 0; j < 14; j++) {
        int c0 = 2*j, c1 = 2*j + 1;
        float v0 = (c0 < 18) ? __ldg(bp + c0) : ((c0 < 27) ? __ldg(bm + c0 - 18) : 0.f);
        float v1 = (c1 < 18) ? __ldg(bp + c1) : ((c1 < 27) ? __ldg(bm + c1 - 18) : 0.f);
        acc[j] = pack2(v0, v1);
    }

    bool ym = (y > 0), yp = (y < HH-1);
    bool xm = (xx > 0), xp = (xx < WW-1);
    const float* xb = x + (size_t)b*CHW + y*WW + xx;

    for (int c = 0; c < CIN; c++) {
        const float* xc = xb + c*HW;
        float v[9];
        v[0] = (ym && xm) ? xc[-WW-1] : 0.f;
        v[1] = ym ? xc[-WW] : 0.f;
        v[2] = (ym && xp) ? xc[-WW+1] : 0.f;
        v[3] = xm ? xc[-1] : 0.f;
        v[4] = xc[0];
        v[5] = xp ? xc[1] : 0.f;
        v[6] = (yp && xm) ? xc[WW-1] : 0.f;
        v[7] = yp ? xc[WW] : 0.f;
        v[8] = (yp && xp) ? xc[WW+1] : 0.f;
#pragma unroll
        for (int k = 0; k < 9; k++) {
            ull s2 = pack2(v[k], v[k]);
            const ull* wr = (const ull*)(sw + (c*9 + k)*28);
#pragma unroll
            for (int j = 0; j < 14; j++) fma2(acc[j], wr[j], s2);
        }
    }

    float* op = g_off + (size_t)b*27*HW + y*WW + xx;
#pragma unroll
    for (int j = 0; j < 14; j++) {
        float lo, hi; unpack2(lo, hi, acc[j]);
        int c0 = 2*j, c1 = 2*j + 1;
        if (c0 >= 18) lo = 1.f / (1.f + expf(-lo));
        op[c0*HW] = lo;
        if (c1 < 27) {
            if (c1 >= 18) hi = 1.f / (1.f + expf(-hi));
            op[c1*HW] = hi;
        }
    }
}

// ---------------------------------------------------------------------------
// K2: deformable bilinear sampling + 64x576 contraction, one thread per pixel,
//     64 output channels in 32 packed f32x2 accumulators.
// ---------------------------------------------------------------------------
__global__ void __launch_bounds__(384, 1) k2_deform(const float* __restrict__ x) {
    extern __shared__ float sw[];   // KROWS*64 floats (147456 B)
    int tid = threadIdx.x;
    for (int i = tid; i < KROWS*64; i += 384) sw[i] = g_wB[i];
    __syncthreads();

    int p   = blockIdx.x * 384 + tid;
    int b   = p / HW;
    int rem = p - b*HW;
    int y   = rem / WW;
    int xx  = rem - y*WW;

    ull acc[32];
#pragma unroll
    for (int j = 0; j < 32; j++) acc[j] = pack2(0.f, 0.f);

    const float* xb   = x + (size_t)b*CHW;
    const float* offp = g_off + (size_t)b*27*HW + rem;

#pragma unroll 1
    for (int n = 0; n < 9; n++) {
        float offy = __ldg(offp + n*HW);
        float offx = __ldg(offp + (9 + n)*HW);
        float mm   = __ldg(offp + (18 + n)*HW);
        // base coord in padded image: (y+1) + (n/3 - 1), (x+1) + (n%3 - 1)
        float py = (float)(y + n/3) + offy;
        float px = (float)(xx + n%3) + offx;
        float fy = floorf(py), fx = floorf(px);
        float qy0 = fminf(fmaxf(fy,       0.f), 193.f);
        float qy1 = fminf(fmaxf(fy + 1.f, 0.f), 193.f);
        float qx0 = fminf(fmaxf(fx,       0.f), 193.f);
        float qx1 = fminf(fmaxf(fx + 1.f, 0.f), 193.f);
        float pyc = fminf(fmaxf(py, 0.f), 193.f);
        float pxc = fminf(fmaxf(px, 0.f), 193.f);
        float wy0 = 1.f + (qy0 - pyc);
        float wy1 = 1.f - (qy1 - pyc);
        float wx0 = 1.f + (qx0 - pxc);
        float wx1 = 1.f - (qx1 - pxc);
        int iy0 = (int)qy0, iy1 = (int)qy1, ix0 = (int)qx0, ix1 = (int)qx1;
        bool vy0 = (iy0 >= 1) && (iy0 <= 192);
        bool vy1 = (iy1 >= 1) && (iy1 <= 192);
        bool vx0 = (ix0 >= 1) && (ix0 <= 192);
        bool vx1 = (ix1 >= 1) && (ix1 <= 192);
        float c00 = (vy0 && vx0) ? wy0*wx0*mm : 0.f;   // gather(qy0,qx0) * g_lt
        float c01 = (vy0 && vx1) ? wy0*wx1*mm : 0.f;   // gather(qy0,qx1) * g_lb
        float c10 = (vy1 && vx0) ? wy1*wx0*mm : 0.f;   // gather(qy1,qx0) * g_rt
        float c11 = (vy1 && vx1) ? wy1*wx1*mm : 0.f;   // gather(qy1,qx1) * g_rb
        int jy0 = min(max(iy0, 1), 192) - 1;
        int jy1 = min(max(iy1, 1), 192) - 1;
        int jx0 = min(max(ix0, 1), 192) - 1;
        int jx1 = min(max(ix1, 1), 192) - 1;
        int o00 = jy0*WW + jx0, o01 = jy0*WW + jx1;
        int o10 = jy1*WW + jx0, o11 = jy1*WW + jx1;

        const float* wsn = sw + n*64;
#pragma unroll 2
        for (int c = 0; c < CIN; c++) {
            const float* xc = xb + c*HW;
            float s = c00*__ldg(xc + o00) + c01*__ldg(xc + o01)
                    + c10*__ldg(xc + o10) + c11*__ldg(xc + o11);
            ull s2 = pack2(s, s);
            const ulonglong2* wr = (const ulonglong2*)(wsn + c*576);
#pragma unroll
            for (int j2 = 0; j2 < 16; j2++) {
                ulonglong2 wv = wr[j2];
                fma2(acc[2*j2],     wv.x, s2);
                fma2(acc[2*j2 + 1], wv.y, s2);
            }
        }
    }

    float* op = g_mid + (size_t)b*COUT*HW + rem;
#pragma unroll
    for (int j = 0; j < 32; j++) {
        float lo, hi; unpack2(lo, hi, acc[j]);
        op[(2*j)*HW]     = lo;
        op[(2*j + 1)*HW] = hi;
    }
}

// ---------------------------------------------------------------------------
// K3/K4: deterministic per-channel BN statistics
// ---------------------------------------------------------------------------
__global__ void k3_stats() {
    int c = blockIdx.x, s = blockIdx.y;
    int tid = threadIdx.x;                 // 256
    float sum = 0.f, sq = 0.f;
    int beg = s * 9216, end = beg + 9216;  // 147456 / 16
    for (int i = beg + tid; i < end; i += 256) {
        int b = i / HW, pos = i - b*HW;
        float v = g_mid[(size_t)b*COUT*HW + c*HW + pos];
        sum += v; sq += v*v;
    }
    __shared__ float ssum[256], ssq[256];
    ssum[tid] = sum; ssq[tid] = sq;
    __syncthreads();
    for (int st = 128; st > 0; st >>= 1) {
        if (tid < st) { ssum[tid] += ssum[tid+st]; ssq[tid] += ssq[tid+st]; }
        __syncthreads();
    }
    if (tid == 0) {
        g_part[(c*16 + s)*2]     = ssum[0];
        g_part[(c*16 + s)*2 + 1] = ssq[0];
    }
}

__global__ void k4_finalize(const float* __restrict__ gamma,
                            const float* __restrict__ beta) {
    int c = threadIdx.x;
    if (c < COUT) {
        float sum = 0.f, sq = 0.f;
        for (int s = 0; s < 16; s++) {
            sum += g_part[(c*16 + s)*2];
            sq  += g_part[(c*16 + s)*2 + 1];
        }
        const float inv = 1.f / (float)PIX;
        float mu  = sum * inv;
        float var = sq * inv - mu*mu;
        float sc  = __ldg(gamma + c) * rsqrtf(var + 1e-5f);
        g_scale[c] = sc;
        g_shift[c] = __ldg(beta + c) - mu * sc;
    }
}

// ---------------------------------------------------------------------------
// K5: BN affine + ReLU + 2x2 maxpool
// ---------------------------------------------------------------------------
__global__ void k5_pool(float* __restrict__ out) {
    int idx = blockIdx.x * 256 + threadIdx.x;
    if (idx >= BATCH*COUT*96*96) return;
    int xo = idx % 96;
    int yo = (idx / 96) % 96;
    int c  = (idx / (96*96)) % COUT;
    int b  = idx / (96*96*COUT);
    float sc = g_scale[c], sh = g_shift[c];
    const float* ip = g_mid + ((size_t)(b*COUT + c))*HW + (2*yo)*WW + 2*xo;
    float v0 = fmaxf(fmaf(ip[0],    sc, sh), 0.f);
    float v1 = fmaxf(fmaf(ip[1],    sc, sh), 0.f);
    float v2 = fmaxf(fmaf(ip[WW],   sc, sh), 0.f);
    float v3 = fmaxf(fmaf(ip[WW+1], sc, sh), 0.f);
    out[idx] = fmaxf(fmaxf(v0, v1), fmaxf(v2, v3));
}

// ---------------------------------------------------------------------------
extern "C" void kernel_launch(void* const* d_in, const int* in_sizes, int n_in,
                              void* d_out, int out_size) {
    const float* x     = (const float*)d_in[0];
    const float* wp    = (const float*)d_in[1];
    const float* bp    = (const float*)d_in[2];
    const float* wm    = (const float*)d_in[3];
    const float* bm    = (const float*)d_in[4];
    const float* wc    = (const float*)d_in[5];
    const float* gamma = (const float*)d_in[6];
    const float* beta  = (const float*)d_in[7];
    float* out = (float*)d_out;

    cudaFuncSetAttribute(k1_offconv, cudaFuncAttributeMaxDynamicSharedMemorySize,
                         KROWS*28*(int)sizeof(float));
    cudaFuncSetAttribute(k2_deform, cudaFuncAttributeMaxDynamicSharedMemorySize,
                         KROWS*64*(int)sizeof(float));

    k0_prep<<<(KROWS*64 + 255)/256, 256>>>(wp, wm, wc);
    k1_offconv<<<dim3(HH, BATCH), 192, KROWS*28*sizeof(float)>>>(x, bp, bm);
    k2_deform<<<PIX/384, 384, KROWS*64*sizeof(float)>>>(x);
    k3_stats<<<dim3(64, 16), 256>>>();
    k4_finalize<<<1, 64>>>(gamma, beta);
    k5_pool<<<(BATCH*COUT*96*96 + 255)/256, 256>>>(out);
}

// round 6
// speedup vs baseline: 1.0016x; 1.0016x over previous
#include <cuda_runtime.h>
#include <math.h>

#define BATCH 4
#define CIN 64
#define COUT 64
#define HH 192
#define WW 192
#define HW (HH*WW)          // 36864
#define CHW (CIN*HW)
#define PIX (BATCH*HW)      // 147456
#define KROWS 576           // cin*9

typedef unsigned long long ull;

__device__ __forceinline__ void fma2(ull &d, ull a, ull b) {
    asm("fma.rn.f32x2 %0, %1, %2, %0;" : "+l"(d) : "l"(a), "l"(b));
}
__device__ __forceinline__ ull pack2(float lo, float hi) {
    ull r; asm("mov.b64 %0, {%1, %2};" : "=l"(r) : "f"(lo), "f"(hi)); return r;
}
__device__ __forceinline__ void unpack2(float &lo, float &hi, ull v) {
    asm("mov.b64 {%0, %1}, %2;" : "=f"(lo), "=f"(hi) : "l"(v));
}

// ---- scratch (device globals; no runtime allocation) ----
__device__ float g_wA[KROWS*28];        // offset/mask weights, [cin*9][28] (27 used)
__device__ float g_wB[KROWS*64];        // main conv weights, [cin*9][64]
__device__ float g_off[BATCH*27*HW];    // 0..8: dy, 9..17: dx, 18..26: sigmoid(mask)
__device__ float g_mid[BATCH*COUT*HW];  // pre-BN conv output
__device__ float g_part[64*16*2];       // BN partial sums
__device__ float g_scale[COUT];
__device__ float g_shift[COUT];

// ---------------------------------------------------------------------------
// K0: transpose weights into [cin*9][oc] layouts
// ---------------------------------------------------------------------------
__global__ void k0_prep(const float* __restrict__ wp, const float* __restrict__ wm,
                        const float* __restrict__ wc) {
    int i = blockIdx.x * 256 + threadIdx.x;
    if (i < KROWS*28) {
        int row = i / 28, j = i % 28;          // row = c*9+k
        float v = 0.f;
        if (j < 18)      v = wp[j*KROWS + row];
        else if (j < 27) v = wm[(j-18)*KROWS + row];
        g_wA[i] = v;
    }
    if (i < KROWS*64) {
        int row = i / 64, o = i % 64;          // row = c*9+n
        g_wB[i] = wc[o*KROWS + row];
    }
}

// ---------------------------------------------------------------------------
// K1: 3x3 conv producing 18 offsets + 9 masks (sigmoid applied), layout
//     g_off[b][j][y][x]
// ---------------------------------------------------------------------------
__global__ void __launch_bounds__(192) k1_offconv(const float* __restrict__ x,
                                                  const float* __restrict__ bp,
                                                  const float* __restrict__ bm) {
    extern __shared__ float sw[];   // KROWS*28 floats
    int tid = threadIdx.x;
    for (int i = tid; i < KROWS*28; i += 192) sw[i] = g_wA[i];
    __syncthreads();

    int xx = tid;
    int y  = blockIdx.x;
    int b  = blockIdx.y;

    ull acc[14];
#pragma unroll
    for (int j = 0; j < 14; j++) {
        int c0 = 2*j, c1 = 2*j + 1;
        float v0 = (c0 < 18) ? __ldg(bp + c0) : ((c0 < 27) ? __ldg(bm + c0 - 18) : 0.f);
        float v1 = (c1 < 18) ? __ldg(bp + c1) : ((c1 < 27) ? __ldg(bm + c1 - 18) : 0.f);
        acc[j] = pack2(v0, v1);
    }

    bool ym = (y > 0), yp = (y < HH-1);
    bool xm = (xx > 0), xp = (xx < WW-1);
    const float* xb = x + (size_t)b*CHW + y*WW + xx;

    for (int c = 0; c < CIN; c++) {
        const float* xc = xb + c*HW;
        float v[9];
        v[0] = (ym && xm) ? xc[-WW-1] : 0.f;
        v[1] = ym ? xc[-WW] : 0.f;
        v[2] = (ym && xp) ? xc[-WW+1] : 0.f;
        v[3] = xm ? xc[-1] : 0.f;
        v[4] = xc[0];
        v[5] = xp ? xc[1] : 0.f;
        v[6] = (yp && xm) ? xc[WW-1] : 0.f;
        v[7] = yp ? xc[WW] : 0.f;
        v[8] = (yp && xp) ? xc[WW+1] : 0.f;
#pragma unroll
        for (int k = 0; k < 9; k++) {
            ull s2 = pack2(v[k], v[k]);
            const ull* wr = (const ull*)(sw + (c*9 + k)*28);
#pragma unroll
            for (int j = 0; j < 14; j++) fma2(acc[j], wr[j], s2);
        }
    }

    float* op = g_off + (size_t)b*27*HW + y*WW + xx;
#pragma unroll
    for (int j = 0; j < 14; j++) {
        float lo, hi; unpack2(lo, hi, acc[j]);
        int c0 = 2*j, c1 = 2*j + 1;
        if (c0 >= 18) lo = 1.f / (1.f + expf(-lo));
        op[c0*HW] = lo;
        if (c1 < 27) {
            if (c1 >= 18) hi = 1.f / (1.f + expf(-hi));
            op[c1*HW] = hi;
        }
    }
}

// ---------------------------------------------------------------------------
// K2: deformable bilinear sampling + 64x576 contraction, one thread per pixel,
//     64 output channels in 32 packed f32x2 accumulators.
// ---------------------------------------------------------------------------
__global__ void __launch_bounds__(384, 1) k2_deform(const float* __restrict__ x) {
    extern __shared__ float sw[];   // KROWS*64 floats (147456 B)
    int tid = threadIdx.x;
    for (int i = tid; i < KROWS*64; i += 384) sw[i] = g_wB[i];
    __syncthreads();

    int p   = blockIdx.x * 384 + tid;
    int b   = p / HW;
    int rem = p - b*HW;
    int y   = rem / WW;
    int xx  = rem - y*WW;

    ull acc[32];
#pragma unroll
    for (int j = 0; j < 32; j++) acc[j] = pack2(0.f, 0.f);

    const float* xb   = x + (size_t)b*CHW;
    const float* offp = g_off + (size_t)b*27*HW + rem;

#pragma unroll 1
    for (int n = 0; n < 9; n++) {
        float offy = __ldg(offp + n*HW);
        float offx = __ldg(offp + (9 + n)*HW);
        float mm   = __ldg(offp + (18 + n)*HW);
        // base coord in padded image: (y+1) + (n/3 - 1), (x+1) + (n%3 - 1)
        float py = (float)(y + n/3) + offy;
        float px = (float)(xx + n%3) + offx;
        float fy = floorf(py), fx = floorf(px);
        float qy0 = fminf(fmaxf(fy,       0.f), 193.f);
        float qy1 = fminf(fmaxf(fy + 1.f, 0.f), 193.f);
        float qx0 = fminf(fmaxf(fx,       0.f), 193.f);
        float qx1 = fminf(fmaxf(fx + 1.f, 0.f), 193.f);
        float pyc = fminf(fmaxf(py, 0.f), 193.f);
        float pxc = fminf(fmaxf(px, 0.f), 193.f);
        float wy0 = 1.f + (qy0 - pyc);
        float wy1 = 1.f - (qy1 - pyc);
        float wx0 = 1.f + (qx0 - pxc);
        float wx1 = 1.f - (qx1 - pxc);
        int iy0 = (int)qy0, iy1 = (int)qy1, ix0 = (int)qx0, ix1 = (int)qx1;
        bool vy0 = (iy0 >= 1) && (iy0 <= 192);
        bool vy1 = (iy1 >= 1) && (iy1 <= 192);
        bool vx0 = (ix0 >= 1) && (ix0 <= 192);
        bool vx1 = (ix1 >= 1) && (ix1 <= 192);
        float c00 = (vy0 && vx0) ? wy0*wx0*mm : 0.f;   // gather(qy0,qx0) * g_lt
        float c01 = (vy0 && vx1) ? wy0*wx1*mm : 0.f;   // gather(qy0,qx1) * g_lb
        float c10 = (vy1 && vx0) ? wy1*wx0*mm : 0.f;   // gather(qy1,qx0) * g_rt
        float c11 = (vy1 && vx1) ? wy1*wx1*mm : 0.f;   // gather(qy1,qx1) * g_rb
        int jy0 = min(max(iy0, 1), 192) - 1;
        int jy1 = min(max(iy1, 1), 192) - 1;
        int jx0 = min(max(ix0, 1), 192) - 1;
        int jx1 = min(max(ix1, 1), 192) - 1;
        int o00 = jy0*WW + jx0, o01 = jy0*WW + jx1;
        int o10 = jy1*WW + jx0, o11 = jy1*WW + jx1;

        const float* wsn = sw + n*64;
#pragma unroll 2
        for (int c = 0; c < CIN; c++) {
            const float* xc = xb + c*HW;
            float s = c00*__ldg(xc + o00) + c01*__ldg(xc + o01)
                    + c10*__ldg(xc + o10) + c11*__ldg(xc + o11);
            ull s2 = pack2(s, s);
            const ulonglong2* wr = (const ulonglong2*)(wsn + c*576);
#pragma unroll
            for (int j2 = 0; j2 < 16; j2++) {
                ulonglong2 wv = wr[j2];
                fma2(acc[2*j2],     wv.x, s2);
                fma2(acc[2*j2 + 1], wv.y, s2);
            }
        }
    }

    float* op = g_mid + (size_t)b*COUT*HW + rem;
#pragma unroll
    for (int j = 0; j < 32; j++) {
        float lo, hi; unpack2(lo, hi, acc[j]);
        op[(2*j)*HW]     = lo;
        op[(2*j + 1)*HW] = hi;
    }
}

// ---------------------------------------------------------------------------
// K3/K4: deterministic per-channel BN statistics
// ---------------------------------------------------------------------------
__global__ void k3_stats() {
    int c = blockIdx.x, s = blockIdx.y;
    int tid = threadIdx.x;                 // 256
    float sum = 0.f, sq = 0.f;
    int beg = s * 9216, end = beg + 9216;  // 147456 / 16
    for (int i = beg + tid; i < end; i += 256) {
        int b = i / HW, pos = i - b*HW;
        float v = g_mid[(size_t)b*COUT*HW + c*HW + pos];
        sum += v; sq += v*v;
    }
    __shared__ float ssum[256], ssq[256];
    ssum[tid] = sum; ssq[tid] = sq;
    __syncthreads();
    for (int st = 128; st > 0; st >>= 1) {
        if (tid < st) { ssum[tid] += ssum[tid+st]; ssq[tid] += ssq[tid+st]; }
        __syncthreads();
    }
    if (tid == 0) {
        g_part[(c*16 + s)*2]     = ssum[0];
        g_part[(c*16 + s)*2 + 1] = ssq[0];
    }
}

__global__ void k4_finalize(const float* __restrict__ gamma,
                            const float* __restrict__ beta) {
    int c = threadIdx.x;
    if (c < COUT) {
        float sum = 0.f, sq = 0.f;
        for (int s = 0; s < 16; s++) {
            sum += g_part[(c*16 + s)*2];
            sq  += g_part[(c*16 + s)*2 + 1];
        }
        const float inv = 1.f / (float)PIX;
        float mu  = sum * inv;
        float var = sq * inv - mu*mu;
        float sc  = __ldg(gamma + c) * rsqrtf(var + 1e-5f);
        g_scale[c] = sc;
        g_shift[c] = __ldg(beta + c) - mu * sc;
    }
}

// ---------------------------------------------------------------------------
// K5: BN affine + ReLU + 2x2 maxpool
// ---------------------------------------------------------------------------
__global__ void k5_pool(float* __restrict__ out) {
    int idx = blockIdx.x * 256 + threadIdx.x;
    if (idx >= BATCH*COUT*96*96) return;
    int xo = idx % 96;
    int yo = (idx / 96) % 96;
    int c  = (idx / (96*96)) % COUT;
    int b  = idx / (96*96*COUT);
    float sc = g_scale[c], sh = g_shift[c];
    const float* ip = g_mid + ((size_t)(b*COUT + c))*HW + (2*yo)*WW + 2*xo;
    float v0 = fmaxf(fmaf(ip[0],    sc, sh), 0.f);
    float v1 = fmaxf(fmaf(ip[1],    sc, sh), 0.f);
    float v2 = fmaxf(fmaf(ip[WW],   sc, sh), 0.f);
    float v3 = fmaxf(fmaf(ip[WW+1], sc, sh), 0.f);
    out[idx] = fmaxf(fmaxf(v0, v1), fmaxf(v2, v3));
}

// ---------------------------------------------------------------------------
extern "C" void kernel_launch(void* const* d_in, const int* in_sizes, int n_in,
                              void* d_out, int out_size) {
    const float* x     = (const float*)d_in[0];
    const float* wp    = (const float*)d_in[1];
    const float* bp    = (const float*)d_in[2];
    const float* wm    = (const float*)d_in[3];
    const float* bm    = (const float*)d_in[4];
    const float* wc    = (const float*)d_in[5];
    const float* gamma = (const float*)d_in[6];
    const float* beta  = (const float*)d_in[7];
    float* out = (float*)d_out;

    cudaFuncSetAttribute(k1_offconv, cudaFuncAttributeMaxDynamicSharedMemorySize,
                         KROWS*28*(int)sizeof(float));
    cudaFuncSetAttribute(k2_deform, cudaFuncAttributeMaxDynamicSharedMemorySize,
                         KROWS*64*(int)sizeof(float));

    k0_prep<<<(KROWS*64 + 255)/256, 256>>>(wp, wm, wc);
    k1_offconv<<<dim3(HH, BATCH), 192, KROWS*28*sizeof(float)>>>(x, bp, bm);
    k2_deform<<<PIX/384, 384, KROWS*64*sizeof(float)>>>(x);
    k3_stats<<<dim3(64, 16), 256>>>();
    k4_finalize<<<1, 64>>>(gamma, beta);
    k5_pool<<<(BATCH*COUT*96*96 + 255)/256, 256>>>(out);
}

// round 9
// speedup vs baseline: 1.4383x; 1.4360x over previous
#include <cuda_runtime.h>
#include <cuda_fp16.h>
#include <math.h>
#include <stdint.h>

#define BATCH 4
#define CIN 64
#define COUT 64
#define HH 192
#define WW 192
#define HW (HH*WW)          // 36864
#define CHW (CIN*HW)
#define PIX (BATCH*HW)      // 147456
#define KROWS 576           // cin*9
#define NTILE2 (PIX/256)    // 576 tiles of 256 pixels
#define BPITCH 580          // B2 row pitch in u32 (576 + 4 pad -> conflict-free)
#define SMEM_B2 (64*BPITCH*4)          // 148480 B
#define SMEM_A  (256*128)              // 32768 B per stage buffer
#define SMEM_K2 (SMEM_B2 + 2*SMEM_A)   // 214016 B

typedef unsigned long long ull;

__device__ __forceinline__ void fma2(ull &d, ull a, ull b) {
    asm("fma.rn.f32x2 %0, %1, %2, %0;" : "+l"(d) : "l"(a), "l"(b));
}
__device__ __forceinline__ ull pack2(float lo, float hi) {
    ull r; asm("mov.b64 %0, {%1, %2};" : "=l"(r) : "f"(lo), "f"(hi)); return r;
}
__device__ __forceinline__ void unpack2(float &lo, float &hi, ull v) {
    asm("mov.b64 {%0, %1}, %2;" : "=f"(lo), "=f"(hi) : "l"(v));
}
__device__ __forceinline__ uint32_t smem_u32(const void* p) {
    uint32_t a;
    asm("{ .reg .u64 t; cvta.to.shared.u64 t, %1; cvt.u32.u64 %0, t; }" : "=r"(a) : "l"(p));
    return a;
}

// ---- scratch (device globals; no runtime allocation) ----
__device__ float    g_wA[KROWS*28];      // offset/mask weights [cin*9][28]
__device__ uint32_t g_wB2[64*BPITCH];    // main weights: dup f16 pairs, [o][u], u=tap*64+c
__device__ float    g_off[BATCH*27*HW];  // 0..8 dy, 9..17 dx, 18..26 sigmoid(mask)
__device__ float    g_mid[BATCH*COUT*HW];
__device__ float    g_part[64*16*2];
__device__ float    g_scale[COUT];
__device__ float    g_shift[COUT];

// ---------------------------------------------------------------------------
// K0: weight prep
// ---------------------------------------------------------------------------
__global__ void k0_prep(const float* __restrict__ wp, const float* __restrict__ wm,
                        const float* __restrict__ wc) {
    int i = blockIdx.x * 256 + threadIdx.x;
    if (i < KROWS*28) {
        int row = i / 28, j = i % 28;
        float v = 0.f;
        if (j < 18)      v = wp[j*KROWS + row];
        else if (j < 27) v = wm[(j-18)*KROWS + row];
        g_wA[i] = v;
    }
    if (i < 64*BPITCH) {
        int n = i / BPITCH, u = i - n*BPITCH;
        uint32_t val = 0;
        if (u < 576) {
            int tap = u >> 6, c = u & 63;
            __half h = __float2half_rn(wc[n*KROWS + c*9 + tap]);
            uint32_t hu = (uint32_t)__half_as_ushort(h);
            val = hu | (hu << 16);
        }
        g_wB2[n*BPITCH + u] = val;
    }
}

// ---------------------------------------------------------------------------
// K1: 3x3 conv -> 18 offsets + 9 masks (sigmoid), g_off[b][j][y][x]  (SIMT f32x2)
// ---------------------------------------------------------------------------
__global__ void __launch_bounds__(192) k1_offconv(const float* __restrict__ x,
                                                  const float* __restrict__ bp,
                                                  const float* __restrict__ bm) {
    extern __shared__ float sw[];
    int tid = threadIdx.x;
    for (int i = tid; i < KROWS*28; i += 192) sw[i] = g_wA[i];
    __syncthreads();

    int xx = tid, y = blockIdx.x, b = blockIdx.y;
    ull acc[14];
#pragma unroll
    for (int j = 0; j < 14; j++) {
        int c0 = 2*j, c1 = 2*j + 1;
        float v0 = (c0 < 18) ? __ldg(bp + c0) : ((c0 < 27) ? __ldg(bm + c0 - 18) : 0.f);
        float v1 = (c1 < 18) ? __ldg(bp + c1) : ((c1 < 27) ? __ldg(bm + c1 - 18) : 0.f);
        acc[j] = pack2(v0, v1);
    }
    bool ym = (y > 0), yp = (y < HH-1);
    bool xm = (xx > 0), xp = (xx < WW-1);
    const float* xb = x + (size_t)b*CHW + y*WW + xx;
    for (int c = 0; c < CIN; c++) {
        const float* xc = xb + c*HW;
        float v[9];
        v[0] = (ym && xm) ? xc[-WW-1] : 0.f;
        v[1] = ym ? xc[-WW] : 0.f;
        v[2] = (ym && xp) ? xc[-WW+1] : 0.f;
        v[3] = xm ? xc[-1] : 0.f;
        v[4] = xc[0];
        v[5] = xp ? xc[1] : 0.f;
        v[6] = (yp && xm) ? xc[WW-1] : 0.f;
        v[7] = yp ? xc[WW] : 0.f;
        v[8] = (yp && xp) ? xc[WW+1] : 0.f;
#pragma unroll
        for (int k = 0; k < 9; k++) {
            ull s2 = pack2(v[k], v[k]);
            const ull* wr = (const ull*)(sw + (c*9 + k)*28);
#pragma unroll
            for (int j = 0; j < 14; j++) fma2(acc[j], wr[j], s2);
        }
    }
    float* op = g_off + (size_t)b*27*HW + y*WW + xx;
#pragma unroll
    for (int j = 0; j < 14; j++) {
        float lo, hi; unpack2(lo, hi, acc[j]);
        int c0 = 2*j, c1 = 2*j + 1;
        if (c0 >= 18) lo = 1.f / (1.f + expf(-lo));
        op[c0*HW] = lo;
        if (c1 < 27) {
            if (c1 >= 18) hi = 1.f / (1.f + expf(-hi));
            op[c1*HW] = hi;
        }
    }
}

// ---------------------------------------------------------------------------
// K2: deformable sampling producer + HMMA (mma.sync m16n8k16) consumer.
//   Tile: M=256 pixels, N=64 outs, K=1152 (cols 2u=sh, 2u+1=sl of sample u,
//   u = tap*64 + c). B dup-f16(w) in both cols -> D = sum (sh+sl)*f16(w).
//   A stage: [256 pix][64 cols f16] = 32KB, SW128 swizzle, double buffered.
//   18 stages (per stage: one tap, 32 channels). 512 threads, 16 M-warps.
// ---------------------------------------------------------------------------
__global__ void __launch_bounds__(512, 1) k2_mma(const float* __restrict__ x) {
    extern __shared__ __align__(1024) char smraw[];
    uint32_t* B2s = (uint32_t*)smraw;               // 148480 B
    const uint32_t AbaseS = smem_u32(smraw) + SMEM_B2;

    int tid = threadIdx.x;
    {   // B2 -> smem
        const uint4* src = (const uint4*)g_wB2;
        uint4* dst = (uint4*)B2s;
        for (int i = tid; i < (64*BPITCH)/4; i += 512) dst[i] = src[i];
    }
    __syncthreads();

    int tile = blockIdx.x;
    int lp   = tid & 255;          // producer pixel within tile
    int uh   = tid >> 8;           // producer u-half (0/1)
    int b    = tile / 144;
    int rembase = (tile - b*144) * 256;
    int rem  = rembase + lp;
    int y    = rem / WW, xx = rem - y*WW;
    const float* xb   = x + (size_t)b*CHW;
    const float* offp = g_off + (size_t)b*27*HW + rem;

    int lane = tid & 31, w = tid >> 5;
    int g = lane >> 2, tig = lane & 3;

    float d[32];
#pragma unroll
    for (int i = 0; i < 32; i++) d[i] = 0.f;

    float cw0=0, cw1=0, cw2=0, cw3=0;
    int   co0=0, co1=0, co2=0, co3=0;

    // ---------------- pipeline ----------------
#pragma unroll 1
    for (int s = -1; s < 18; s++) {
        // ---- MMA consume stage s (skipped for s = -1) ----
        if (s >= 0) {
            int bufo = (s & 1) * SMEM_A;
#pragma unroll
            for (int kc = 0; kc < 4; kc++) {
                uint32_t lrow = (uint32_t)(w*16 + (lane & 15));
                uint32_t colb = (uint32_t)(kc*32 + ((lane & 16) ? 16 : 0));
                uint32_t byte = lrow*128u + colb;
                byte ^= ((byte >> 3) & 0x70u);
                uint32_t a0, a1, a2, a3;
                asm volatile(
                    "ldmatrix.sync.aligned.m8n8.x4.shared.b16 {%0,%1,%2,%3}, [%4];"
                    : "=r"(a0), "=r"(a1), "=r"(a2), "=r"(a3)
                    : "r"(AbaseS + (uint32_t)bufo + byte));
                int ub = s*32 + kc*8 + tig;
#pragma unroll
                for (int nt = 0; nt < 8; nt++) {
                    int nrow = nt*8 + g;
                    uint32_t b0 = B2s[nrow*BPITCH + ub];
                    uint32_t b1 = B2s[nrow*BPITCH + ub + 4];
                    asm volatile(
                        "mma.sync.aligned.m16n8k16.row.col.f32.f16.f16.f32 "
                        "{%0,%1,%2,%3}, {%4,%5,%6,%7}, {%8,%9}, {%0,%1,%2,%3};"
                        : "+f"(d[nt*4+0]), "+f"(d[nt*4+1]),
                          "+f"(d[nt*4+2]), "+f"(d[nt*4+3])
                        : "r"(a0), "r"(a1), "r"(a2), "r"(a3), "r"(b0), "r"(b1));
                }
            }
        }
        // ---- produce stage s+1 ----
        int sp = s + 1;
        if (sp < 18) {
            int n = sp >> 1;
            if ((sp & 1) == 0) {   // new tap: recompute corners for this pixel
                float offy = __ldg(offp + n*HW);
                float offx = __ldg(offp + (9+n)*HW);
                float mm   = __ldg(offp + (18+n)*HW);
                int ty = n / 3, tx = n - 3*ty;
                float py = (float)(y + ty) + offy;
                float px = (float)(xx + tx) + offx;
                float fy = floorf(py), fx = floorf(px);
                float qy0 = fminf(fmaxf(fy,       0.f), 193.f);
                float qy1 = fminf(fmaxf(fy + 1.f, 0.f), 193.f);
                float qx0 = fminf(fmaxf(fx,       0.f), 193.f);
                float qx1 = fminf(fmaxf(fx + 1.f, 0.f), 193.f);
                float pyc = fminf(fmaxf(py, 0.f), 193.f);
                float pxc = fminf(fmaxf(px, 0.f), 193.f);
                float wy0 = 1.f + (qy0 - pyc), wy1 = 1.f - (qy1 - pyc);
                float wx0 = 1.f + (qx0 - pxc), wx1 = 1.f - (qx1 - pxc);
                int iy0 = (int)qy0, iy1 = (int)qy1, ix0 = (int)qx0, ix1 = (int)qx1;
                bool vy0 = (iy0 >= 1) && (iy0 <= 192);
                bool vy1 = (iy1 >= 1) && (iy1 <= 192);
                bool vx0 = (ix0 >= 1) && (ix0 <= 192);
                bool vx1 = (ix1 >= 1) && (ix1 <= 192);
                cw0 = (vy0 && vx0) ? wy0*wx0*mm : 0.f;
                cw1 = (vy0 && vx1) ? wy0*wx1*mm : 0.f;
                cw2 = (vy1 && vx0) ? wy1*wx0*mm : 0.f;
                cw3 = (vy1 && vx1) ? wy1*wx1*mm : 0.f;
                int jy0 = min(max(iy0, 1), 192) - 1;
                int jy1 = min(max(iy1, 1), 192) - 1;
                int jx0 = min(max(ix0, 1), 192) - 1;
                int jx1 = min(max(ix1, 1), 192) - 1;
                co0 = jy0*WW + jx0; co1 = jy0*WW + jx1;
                co2 = jy1*WW + jx0; co3 = jy1*WW + jx1;
            }
            int chalf = (sp & 1) * 32;
            uint32_t Abuf = AbaseS + (uint32_t)((sp & 1) * SMEM_A);
#pragma unroll
            for (int q = 0; q < 4; q++) {
                uint32_t v[4];
#pragma unroll
                for (int ci = 0; ci < 4; ci++) {
                    int c = chalf + uh*16 + q*4 + ci;
                    const float* xc = xb + (size_t)c*HW;
                    float sv = cw0*__ldg(xc + co0) + cw1*__ldg(xc + co1)
                             + cw2*__ldg(xc + co2) + cw3*__ldg(xc + co3);
                    __half hh = __float2half_rn(sv);
                    __half ll = __float2half_rn(sv - __half2float(hh));
                    v[ci] = (uint32_t)__half_as_ushort(hh)
                          | ((uint32_t)__half_as_ushort(ll) << 16);
                }
                uint32_t byte = (uint32_t)lp*128u + (uint32_t)(uh*64 + q*16);
                byte ^= ((byte >> 3) & 0x70u);
                asm volatile("st.shared.v4.b32 [%0], {%1,%2,%3,%4};"
                    :: "r"(Abuf + byte), "r"(v[0]), "r"(v[1]), "r"(v[2]), "r"(v[3])
                    : "memory");
            }
        }
        __syncthreads();
    }

    // ---- writeout D: warp w owns pixels rembase + w*16 + {g, g+8} ----
    float* op = g_mid + (size_t)b*COUT*HW + (rembase + w*16);
#pragma unroll
    for (int nt = 0; nt < 8; nt++) {
        int o0 = nt*8 + 2*tig;
        op[(size_t)o0*HW     + g    ] = d[nt*4+0];
        op[(size_t)(o0+1)*HW + g    ] = d[nt*4+1];
        op[(size_t)o0*HW     + g + 8] = d[nt*4+2];
        op[(size_t)(o0+1)*HW + g + 8] = d[nt*4+3];
    }
}

// ---------------------------------------------------------------------------
// K3/K4: deterministic BN stats
// ---------------------------------------------------------------------------
__global__ void k3_stats() {
    int c = blockIdx.x, s = blockIdx.y;
    int tid = threadIdx.x;
    float sum = 0.f, sq = 0.f;
    int beg = s * 9216, end = beg + 9216;
    for (int i = beg + tid; i < end; i += 256) {
        int b = i / HW, pos = i - b*HW;
        float v = g_mid[(size_t)b*COUT*HW + c*HW + pos];
        sum += v; sq += v*v;
    }
    __shared__ float ssum[256], ssq[256];
    ssum[tid] = sum; ssq[tid] = sq;
    __syncthreads();
    for (int st = 128; st > 0; st >>= 1) {
        if (tid < st) { ssum[tid] += ssum[tid+st]; ssq[tid] += ssq[tid+st]; }
        __syncthreads();
    }
    if (tid == 0) {
        g_part[(c*16 + s)*2]     = ssum[0];
        g_part[(c*16 + s)*2 + 1] = ssq[0];
    }
}

__global__ void k4_finalize(const float* __restrict__ gamma,
                            const float* __restrict__ beta) {
    int c = threadIdx.x;
    if (c < COUT) {
        float sum = 0.f, sq = 0.f;
        for (int s = 0; s < 16; s++) {
            sum += g_part[(c*16 + s)*2];
            sq  += g_part[(c*16 + s)*2 + 1];
        }
        const float inv = 1.f / (float)PIX;
        float mu  = sum * inv;
        float var = sq * inv - mu*mu;
        float sc  = __ldg(gamma + c) * rsqrtf(var + 1e-5f);
        g_scale[c] = sc;
        g_shift[c] = __ldg(beta + c) - mu * sc;
    }
}

// ---------------------------------------------------------------------------
// K5: BN affine + ReLU + 2x2 maxpool
// ---------------------------------------------------------------------------
__global__ void k5_pool(float* __restrict__ out) {
    int idx = blockIdx.x * 256 + threadIdx.x;
    if (idx >= BATCH*COUT*96*96) return;
    int xo = idx % 96;
    int yo = (idx / 96) % 96;
    int c  = (idx / (96*96)) % COUT;
    int b  = idx / (96*96*COUT);
    float sc = g_scale[c], sh = g_shift[c];
    const float* ip = g_mid + ((size_t)(b*COUT + c))*HW + (2*yo)*WW + 2*xo;
    float v0 = fmaxf(fmaf(ip[0],    sc, sh), 0.f);
    float v1 = fmaxf(fmaf(ip[1],    sc, sh), 0.f);
    float v2 = fmaxf(fmaf(ip[WW],   sc, sh), 0.f);
    float v3 = fmaxf(fmaf(ip[WW+1], sc, sh), 0.f);
    out[idx] = fmaxf(fmaxf(v0, v1), fmaxf(v2, v3));
}

// ---------------------------------------------------------------------------
extern "C" void kernel_launch(void* const* d_in, const int* in_sizes, int n_in,
                              void* d_out, int out_size) {
    const float* x     = (const float*)d_in[0];
    const float* wp    = (const float*)d_in[1];
    const float* bp    = (const float*)d_in[2];
    const float* wm    = (const float*)d_in[3];
    const float* bm    = (const float*)d_in[4];
    const float* wc    = (const float*)d_in[5];
    const float* gamma = (const float*)d_in[6];
    const float* beta  = (const float*)d_in[7];
    float* out = (float*)d_out;

    cudaFuncSetAttribute(k1_offconv, cudaFuncAttributeMaxDynamicSharedMemorySize,
                         KROWS*28*(int)sizeof(float));
    cudaFuncSetAttribute(k2_mma, cudaFuncAttributeMaxDynamicSharedMemorySize,
                         SMEM_K2);

    k0_prep<<<(64*BPITCH + 255)/256, 256>>>(wp, wm, wc);
    k1_offconv<<<dim3(HH, BATCH), 192, KROWS*28*sizeof(float)>>>(x, bp, bm);
    k2_mma<<<NTILE2, 512, SMEM_K2>>>(x);
    k3_stats<<<dim3(64, 16), 256>>>();
    k4_finalize<<<1, 64>>>(gamma, beta);
    k5_pool<<<(BATCH*COUT*96*96 + 255)/256, 256>>>(out);
}

// round 10
// speedup vs baseline: 1.8891x; 1.3134x over previous
#include <cuda_runtime.h>
#include <math.h>
#include <stdint.h>

#define BATCH 4
#define CIN 64
#define COUT 64
#define HH 192
#define WW 192
#define HW (HH*WW)          // 36864
#define CHW (CIN*HW)
#define PIX (BATCH*HW)      // 147456
#define KROWS 576
#define NTILE2 (PIX/256)    // 576 tiles of 256 pixels
#define BPITCH 580          // B row pitch in u32 (576 + 4 pad)
#define SMEM_A  (256*32*4)               // 32 KB per A stage (256 px x 32 tf32)
#define SMEM_B2 (64*BPITCH*4)            // 148480
#define SMEM_B1 (32*BPITCH*4)            // 74240
#define SMEM_K2 (SMEM_B2 + 2*SMEM_A)     // 214016
#define SMEM_K1 (SMEM_B1 + 2*SMEM_A)     // 139776

__device__ __forceinline__ uint32_t smem_u32(const void* p) {
    uint32_t a;
    asm("{ .reg .u64 t; cvta.to.shared.u64 t, %1; cvt.u32.u64 %0, t; }" : "=r"(a) : "l"(p));
    return a;
}
__device__ __forceinline__ uint32_t tf32cvt(float f) {
    uint32_t u; asm("cvt.rna.tf32.f32 %0, %1;" : "=r"(u) : "f"(f)); return u;
}
__device__ __forceinline__ void mma_tf32(float* d, uint32_t a0, uint32_t a1,
                                         uint32_t a2, uint32_t a3,
                                         uint32_t b0, uint32_t b1) {
    asm volatile(
        "mma.sync.aligned.m16n8k8.row.col.f32.tf32.tf32.f32 "
        "{%0,%1,%2,%3}, {%4,%5,%6,%7}, {%8,%9}, {%0,%1,%2,%3};"
        : "+f"(d[0]), "+f"(d[1]), "+f"(d[2]), "+f"(d[3])
        : "r"(a0), "r"(a1), "r"(a2), "r"(a3), "r"(b0), "r"(b1));
}
__device__ __forceinline__ uint32_t swz(uint32_t byte) {
    return byte ^ ((byte >> 3) & 0x70u);
}

// ---- scratch (device globals) ----
__device__ uint32_t g_wB1[32*BPITCH];    // offset/mask weights tf32, [o pad32][u], u=tap*64+c
__device__ uint32_t g_wB2[64*BPITCH];    // main conv weights tf32, [o][u]
__device__ float    g_off[BATCH*27*HW];  // 0..8 dy, 9..17 dx, 18..26 sigmoid(mask)
__device__ float    g_mid[BATCH*COUT*HW];
__device__ float    g_part[64*16*2];
__device__ float    g_scale[COUT];
__device__ float    g_shift[COUT];

// ---------------------------------------------------------------------------
// K0: pack tf32 weight matrices
// ---------------------------------------------------------------------------
__global__ void k0_prep(const float* __restrict__ wp, const float* __restrict__ wm,
                        const float* __restrict__ wc) {
    int i = blockIdx.x * 256 + threadIdx.x;
    if (i < 32*BPITCH) {
        int n = i / BPITCH, u = i - n*BPITCH;
        uint32_t val = 0;
        if (u < 576 && n < 27) {
            int tap = u >> 6, c = u & 63;
            float w = (n < 18) ? wp[n*KROWS + c*9 + tap] : wm[(n-18)*KROWS + c*9 + tap];
            val = tf32cvt(w);
        }
        g_wB1[i] = val;
    }
    if (i < 64*BPITCH) {
        int n = i / BPITCH, u = i - n*BPITCH;
        uint32_t val = 0;
        if (u < 576) {
            int tap = u >> 6, c = u & 63;
            val = tf32cvt(wc[n*KROWS + c*9 + tap]);
        }
        g_wB2[i] = val;
    }
}

// ---------------------------------------------------------------------------
// K1: offset/mask conv as tf32 HMMA GEMM. Tile M=256 px, N=32 (27 used),
//     K=576 (u = tap*64 + c). 18 stages of 32 K-cols, double-buffered A.
// ---------------------------------------------------------------------------
__global__ void __launch_bounds__(512, 1) k1_mma(const float* __restrict__ x,
                                                 const float* __restrict__ bp,
                                                 const float* __restrict__ bm) {
    extern __shared__ __align__(1024) char smraw[];
    uint32_t* B1s = (uint32_t*)smraw;
    const uint32_t AbaseS = smem_u32(smraw) + SMEM_B1;

    int tid = threadIdx.x;
    {
        const uint4* src = (const uint4*)g_wB1;
        uint4* dst = (uint4*)B1s;
        for (int i = tid; i < (32*BPITCH)/4; i += 512) dst[i] = src[i];
    }
    __syncthreads();

    int tile = blockIdx.x;
    int lp   = tid & 255;
    int uh   = tid >> 8;
    int b    = tile / 144;
    int rembase = (tile - b*144) * 256;
    int rem  = rembase + lp;
    int y    = rem / WW, xx = rem - y*WW;
    const float* xb = x + (size_t)b*CHW;

    int lane = tid & 31, w = tid >> 5;
    int r = lane >> 2, t = lane & 3;

    float d[16];
#pragma unroll
    for (int i = 0; i < 16; i++) d[i] = 0.f;

#pragma unroll 1
    for (int s = -1; s < 18; s++) {
        if (s >= 0) {
            uint32_t Abuf = AbaseS + (uint32_t)((s & 1) * SMEM_A);
#pragma unroll
            for (int kc = 0; kc < 4; kc++) {
                uint32_t brow = (uint32_t)(w*16 + r)*128u;
                uint32_t bcol = (uint32_t)(kc*8 + t)*4u;
                uint32_t a0, a1, a2, a3;
                asm volatile("ld.shared.b32 %0, [%1];" : "=r"(a0) : "r"(Abuf + swz(brow + bcol)));
                asm volatile("ld.shared.b32 %0, [%1];" : "=r"(a1) : "r"(Abuf + swz(brow + 1024u + bcol)));
                asm volatile("ld.shared.b32 %0, [%1];" : "=r"(a2) : "r"(Abuf + swz(brow + bcol + 16u)));
                asm volatile("ld.shared.b32 %0, [%1];" : "=r"(a3) : "r"(Abuf + swz(brow + 1024u + bcol + 16u)));
                int ub = s*32 + kc*8 + t;
#pragma unroll
                for (int nt = 0; nt < 4; nt++) {
                    int nrow = nt*8 + r;
                    uint32_t b0 = B1s[nrow*BPITCH + ub];
                    uint32_t b1 = B1s[nrow*BPITCH + ub + 4];
                    mma_tf32(d + nt*4, a0, a1, a2, a3, b0, b1);
                }
            }
        }
        int sp = s + 1;
        if (sp < 18) {
            int n  = sp >> 1;
            int ty = n / 3, tx = n - 3*ty;
            int iy = y + ty - 1, ix = xx + tx - 1;
            bool valid = (iy >= 0) && (iy < HH) && (ix >= 0) && (ix < WW);
            int chalf = (sp & 1) * 32;
            uint32_t Abuf = AbaseS + (uint32_t)((sp & 1) * SMEM_A);
            const float* xs = xb + iy*WW + ix;
#pragma unroll
            for (int q = 0; q < 4; q++) {
                uint32_t v[4];
#pragma unroll
                for (int ci = 0; ci < 4; ci++) {
                    int c = chalf + uh*16 + q*4 + ci;
                    float sv = valid ? __ldg(xs + (size_t)c*HW) : 0.f;
                    v[ci] = tf32cvt(sv);
                }
                uint32_t byte = swz((uint32_t)lp*128u + (uint32_t)(uh*16 + q*4)*4u);
                asm volatile("st.shared.v4.b32 [%0], {%1,%2,%3,%4};"
                    :: "r"(Abuf + byte), "r"(v[0]), "r"(v[1]), "r"(v[2]), "r"(v[3])
                    : "memory");
            }
        }
        __syncthreads();
    }

    // writeout: pixel = rembase + w*16 + {r, r+8}; o = nt*8 + 2*t + {0,1}
    float* op = g_off + (size_t)b*27*HW + (rembase + w*16);
#pragma unroll
    for (int nt = 0; nt < 4; nt++) {
#pragma unroll
        for (int e = 0; e < 2; e++) {
            int o = nt*8 + 2*t + e;
            if (o >= 27) continue;
            float add = (o < 18) ? __ldg(bp + o) : __ldg(bm + o - 18);
            float v0 = d[nt*4 + e]     + add;
            float v1 = d[nt*4 + 2 + e] + add;
            if (o >= 18) {
                v0 = 1.f / (1.f + expf(-v0));
                v1 = 1.f / (1.f + expf(-v1));
            }
            op[(size_t)o*HW + r]     = v0;
            op[(size_t)o*HW + r + 8] = v1;
        }
    }
}

// ---------------------------------------------------------------------------
// K2: deformable sampling + main conv as tf32 HMMA GEMM.
//     Tile M=256 px, N=64, K=576. 18 stages (tap n = s>>1, 32 channels each).
// ---------------------------------------------------------------------------
__global__ void __launch_bounds__(512, 1) k2_mma(const float* __restrict__ x) {
    extern __shared__ __align__(1024) char smraw[];
    uint32_t* B2s = (uint32_t*)smraw;
    const uint32_t AbaseS = smem_u32(smraw) + SMEM_B2;

    int tid = threadIdx.x;
    {
        const uint4* src = (const uint4*)g_wB2;
        uint4* dst = (uint4*)B2s;
        for (int i = tid; i < (64*BPITCH)/4; i += 512) dst[i] = src[i];
    }
    __syncthreads();

    int tile = blockIdx.x;
    int lp   = tid & 255;
    int uh   = tid >> 8;
    int b    = tile / 144;
    int rembase = (tile - b*144) * 256;
    int rem  = rembase + lp;
    int y    = rem / WW, xx = rem - y*WW;
    const float* xb   = x + (size_t)b*CHW;
    const float* offp = g_off + (size_t)b*27*HW + rem;

    int lane = tid & 31, w = tid >> 5;
    int r = lane >> 2, t = lane & 3;

    float d[32];
#pragma unroll
    for (int i = 0; i < 32; i++) d[i] = 0.f;

    float cw0=0, cw1=0, cw2=0, cw3=0;
    int   co0=0, co1=0, co2=0, co3=0;

#pragma unroll 1
    for (int s = -1; s < 18; s++) {
        if (s >= 0) {
            uint32_t Abuf = AbaseS + (uint32_t)((s & 1) * SMEM_A);
#pragma unroll
            for (int kc = 0; kc < 4; kc++) {
                uint32_t brow = (uint32_t)(w*16 + r)*128u;
                uint32_t bcol = (uint32_t)(kc*8 + t)*4u;
                uint32_t a0, a1, a2, a3;
                asm volatile("ld.shared.b32 %0, [%1];" : "=r"(a0) : "r"(Abuf + swz(brow + bcol)));
                asm volatile("ld.shared.b32 %0, [%1];" : "=r"(a1) : "r"(Abuf + swz(brow + 1024u + bcol)));
                asm volatile("ld.shared.b32 %0, [%1];" : "=r"(a2) : "r"(Abuf + swz(brow + bcol + 16u)));
                asm volatile("ld.shared.b32 %0, [%1];" : "=r"(a3) : "r"(Abuf + swz(brow + 1024u + bcol + 16u)));
                int ub = s*32 + kc*8 + t;
#pragma unroll
                for (int nt = 0; nt < 8; nt++) {
                    int nrow = nt*8 + r;
                    uint32_t b0 = B2s[nrow*BPITCH + ub];
                    uint32_t b1 = B2s[nrow*BPITCH + ub + 4];
                    mma_tf32(d + nt*4, a0, a1, a2, a3, b0, b1);
                }
            }
        }
        int sp = s + 1;
        if (sp < 18) {
            int n = sp >> 1;
            if ((sp & 1) == 0) {   // new tap: recompute bilinear corners
                float offy = __ldg(offp + n*HW);
                float offx = __ldg(offp + (9+n)*HW);
                float mm   = __ldg(offp + (18+n)*HW);
                int ty = n / 3, tx = n - 3*ty;
                float py = (float)(y + ty) + offy;
                float px = (float)(xx + tx) + offx;
                float fy = floorf(py), fx = floorf(px);
                float qy0 = fminf(fmaxf(fy,       0.f), 193.f);
                float qy1 = fminf(fmaxf(fy + 1.f, 0.f), 193.f);
                float qx0 = fminf(fmaxf(fx,       0.f), 193.f);
                float qx1 = fminf(fmaxf(fx + 1.f, 0.f), 193.f);
                float pyc = fminf(fmaxf(py, 0.f), 193.f);
                float pxc = fminf(fmaxf(px, 0.f), 193.f);
                float wy0 = 1.f + (qy0 - pyc), wy1 = 1.f - (qy1 - pyc);
                float wx0 = 1.f + (qx0 - pxc), wx1 = 1.f - (qx1 - pxc);
                int iy0 = (int)qy0, iy1 = (int)qy1, ix0 = (int)qx0, ix1 = (int)qx1;
                bool vy0 = (iy0 >= 1) && (iy0 <= 192);
                bool vy1 = (iy1 >= 1) && (iy1 <= 192);
                bool vx0 = (ix0 >= 1) && (ix0 <= 192);
                bool vx1 = (ix1 >= 1) && (ix1 <= 192);
                cw0 = (vy0 && vx0) ? wy0*wx0*mm : 0.f;
                cw1 = (vy0 && vx1) ? wy0*wx1*mm : 0.f;
                cw2 = (vy1 && vx0) ? wy1*wx0*mm : 0.f;
                cw3 = (vy1 && vx1) ? wy1*wx1*mm : 0.f;
                int jy0 = min(max(iy0, 1), 192) - 1;
                int jy1 = min(max(iy1, 1), 192) - 1;
                int jx0 = min(max(ix0, 1), 192) - 1;
                int jx1 = min(max(ix1, 1), 192) - 1;
                co0 = jy0*WW + jx0; co1 = jy0*WW + jx1;
                co2 = jy1*WW + jx0; co3 = jy1*WW + jx1;
            }
            int chalf = (sp & 1) * 32;
            uint32_t Abuf = AbaseS + (uint32_t)((sp & 1) * SMEM_A);
#pragma unroll
            for (int q = 0; q < 4; q++) {
                uint32_t v[4];
#pragma unroll
                for (int ci = 0; ci < 4; ci++) {
                    int c = chalf + uh*16 + q*4 + ci;
                    const float* xc = xb + (size_t)c*HW;
                    float sv = cw0*__ldg(xc + co0) + cw1*__ldg(xc + co1)
                             + cw2*__ldg(xc + co2) + cw3*__ldg(xc + co3);
                    v[ci] = tf32cvt(sv);
                }
                uint32_t byte = swz((uint32_t)lp*128u + (uint32_t)(uh*16 + q*4)*4u);
                asm volatile("st.shared.v4.b32 [%0], {%1,%2,%3,%4};"
                    :: "r"(Abuf + byte), "r"(v[0]), "r"(v[1]), "r"(v[2]), "r"(v[3])
                    : "memory");
            }
        }
        __syncthreads();
    }

    // writeout D: warp w owns pixels rembase + w*16 + {r, r+8}
    float* op = g_mid + (size_t)b*COUT*HW + (rembase + w*16);
#pragma unroll
    for (int nt = 0; nt < 8; nt++) {
        int o0 = nt*8 + 2*t;
        op[(size_t)o0*HW     + r    ] = d[nt*4+0];
        op[(size_t)(o0+1)*HW + r    ] = d[nt*4+1];
        op[(size_t)o0*HW     + r + 8] = d[nt*4+2];
        op[(size_t)(o0+1)*HW + r + 8] = d[nt*4+3];
    }
}

// ---------------------------------------------------------------------------
// K3/K4: deterministic BN stats
// ---------------------------------------------------------------------------
__global__ void k3_stats() {
    int c = blockIdx.x, s = blockIdx.y;
    int tid = threadIdx.x;
    float sum = 0.f, sq = 0.f;
    int beg = s * 9216, end = beg + 9216;
    for (int i = beg + tid; i < end; i += 256) {
        int b = i / HW, pos = i - b*HW;
        float v = g_mid[(size_t)b*COUT*HW + c*HW + pos];
        sum += v; sq += v*v;
    }
    __shared__ float ssum[256], ssq[256];
    ssum[tid] = sum; ssq[tid] = sq;
    __syncthreads();
    for (int st = 128; st > 0; st >>= 1) {
        if (tid < st) { ssum[tid] += ssum[tid+st]; ssq[tid] += ssq[tid+st]; }
        __syncthreads();
    }
    if (tid == 0) {
        g_part[(c*16 + s)*2]     = ssum[0];
        g_part[(c*16 + s)*2 + 1] = ssq[0];
    }
}

__global__ void k4_finalize(const float* __restrict__ gamma,
                            const float* __restrict__ beta) {
    int c = threadIdx.x;
    if (c < COUT) {
        float sum = 0.f, sq = 0.f;
        for (int s = 0; s < 16; s++) {
            sum += g_part[(c*16 + s)*2];
            sq  += g_part[(c*16 + s)*2 + 1];
        }
        const float inv = 1.f / (float)PIX;
        float mu  = sum * inv;
        float var = sq * inv - mu*mu;
        float sc  = __ldg(gamma + c) * rsqrtf(var + 1e-5f);
        g_scale[c] = sc;
        g_shift[c] = __ldg(beta + c) - mu * sc;
    }
}

// ---------------------------------------------------------------------------
// K5: BN affine + ReLU + 2x2 maxpool
// ---------------------------------------------------------------------------
__global__ void k5_pool(float* __restrict__ out) {
    int idx = blockIdx.x * 256 + threadIdx.x;
    if (idx >= BATCH*COUT*96*96) return;
    int xo = idx % 96;
    int yo = (idx / 96) % 96;
    int c  = (idx / (96*96)) % COUT;
    int b  = idx / (96*96*COUT);
    float sc = g_scale[c], sh = g_shift[c];
    const float* ip = g_mid + ((size_t)(b*COUT + c))*HW + (2*yo)*WW + 2*xo;
    float v0 = fmaxf(fmaf(ip[0],    sc, sh), 0.f);
    float v1 = fmaxf(fmaf(ip[1],    sc, sh), 0.f);
    float v2 = fmaxf(fmaf(ip[WW],   sc, sh), 0.f);
    float v3 = fmaxf(fmaf(ip[WW+1], sc, sh), 0.f);
    out[idx] = fmaxf(fmaxf(v0, v1), fmaxf(v2, v3));
}

// ---------------------------------------------------------------------------
extern "C" void kernel_launch(void* const* d_in, const int* in_sizes, int n_in,
                              void* d_out, int out_size) {
    const float* x     = (const float*)d_in[0];
    const float* wp    = (const float*)d_in[1];
    const float* bp    = (const float*)d_in[2];
    const float* wm    = (const float*)d_in[3];
    const float* bm    = (const float*)d_in[4];
    const float* wc    = (const float*)d_in[5];
    const float* gamma = (const float*)d_in[6];
    const float* beta  = (const float*)d_in[7];
    float* out = (float*)d_out;

    cudaFuncSetAttribute(k1_mma, cudaFuncAttributeMaxDynamicSharedMemorySize, SMEM_K1);
    cudaFuncSetAttribute(k2_mma, cudaFuncAttributeMaxDynamicSharedMemorySize, SMEM_K2);

    k0_prep<<<(64*BPITCH + 255)/256, 256>>>(wp, wm, wc);
    k1_mma<<<NTILE2, 512, SMEM_K1>>>(x, bp, bm);
    k2_mma<<<NTILE2, 512, SMEM_K2>>>(x);
    k3_stats<<<dim3(64, 16), 256>>>();
    k4_finalize<<<1, 64>>>(gamma, beta);
    k5_pool<<<(BATCH*COUT*96*96 + 255)/256, 256>>>(out);
}